// round 11
// baseline (speedup 1.0000x reference)
#include <cuda_runtime.h>

#define N_TOK 98
#define CDIM 128
#define HEADS 4
#define LWIN 512
#define NWIN 2048

#define CVT_TF32(u, f) asm("cvt.rna.tf32.f32 %0, %1;" : "=r"(u) : "f"(f))

__device__ __forceinline__ void mma_tf32(float* d, const unsigned* a, const unsigned* b) {
    asm volatile("mma.sync.aligned.m16n8k8.row.col.f32.tf32.tf32.f32 "
        "{%0,%1,%2,%3}, {%4,%5,%6,%7}, {%8,%9}, {%0,%1,%2,%3};"
        : "+f"(d[0]), "+f"(d[1]), "+f"(d[2]), "+f"(d[3])
        : "r"(a[0]), "r"(a[1]), "r"(a[2]), "r"(a[3]), "r"(b[0]), "r"(b[1]));
}

// ------------- global scratch (zero-initialized at module load) -------------
__device__ float g_bias[HEADS * N_TOK * N_TOK];              // bias[h][i][j]
__device__ float g_q [NWIN * HEADS * N_TOK * 32];            // [wh][i][d]    tf32 bits
__device__ float g_kT[NWIN * HEADS * 32 * 104];              // [wh][d][j]    tf32 bits, pads 0
__device__ float g_vT[NWIN * HEADS * 32 * 104];              // [wh][d][j]    tf32 bits, pads 0
__device__ float g_O [NWIN * N_TOK * CDIM];                  // [b][i][(C+4i)&127] tf32 bits

__global__ void bias_precompute_kernel(const float* __restrict__ pe)
{
    int idx = blockIdx.x * blockDim.x + threadIdx.x;
    if (idx >= HEADS * N_TOK * N_TOK) return;
    int h = idx / (N_TOK * N_TOK);
    int r = idx % (N_TOK * N_TOK);
    int i = r / N_TOK, j = r % N_TOK;
    int ti = i / 49, rem = i % 49, hi = rem / 7, wi = rem % 7;
    int tj = j / 49, remj = j % 49, hj = remj / 7, wj = remj % 7;
    int ridx = (ti - tj + 1) * 169 + (hi - hj + 6) * 13 + (wi - wj + 6);
    g_bias[idx] = pe[h * 507 + ridx];
}

// =================== Kernel A: QKV GEMM (grid NWIN, 512 thr) ===================
// smem: xs [0..12544) x tile tf32 bits swizzled; wt [12544..18816) 16x392 chunk
#define A_SMEM_FLOATS 18816

__global__ __launch_bounds__(512)
void qkv_kernel(const float* __restrict__ x,
                const float* __restrict__ qkv_w,
                const float* __restrict__ qkv_b)
{
    extern __shared__ float sm[];
    float* xs = sm;
    float* wt = sm + 12544;

    const int b   = blockIdx.x;
    const int tid = threadIdx.x;
    const int tx  = tid & 31;
    const int ty  = tid >> 5;
    const int gid = tx >> 2;
    const int tig = tx & 3;
    const float scale = 0.17677669529663687f;

    // load x tile (tf32 bits, swizzle col' = (c+4i)&127)
    {
        const float4* xg4 = (const float4*)(x + (size_t)b * (N_TOK * CDIM));
        for (int idx = tid; idx < N_TOK * 32; idx += 512) {
            int i = idx >> 5, j4 = idx & 31;
            float4 v = xg4[i * 32 + j4];
            uint4 u;
            CVT_TF32(u.x, v.x); CVT_TF32(u.y, v.y);
            CVT_TF32(u.z, v.z); CVT_TF32(u.w, v.w);
            int sw = ((j4 * 4 + 4 * i) & 127) >> 2;
            ((uint4*)xs)[i * 32 + sw] = u;
        }
    }

    float facc[7][3][4];
    #pragma unroll
    for (int mt = 0; mt < 7; ++mt)
        #pragma unroll
        for (int nt = 0; nt < 3; ++nt)
            #pragma unroll
            for (int e = 0; e < 4; ++e) facc[mt][nt][e] = 0.f;

    float wreg[12];
    #pragma unroll
    for (int u = 0; u < 12; ++u) {
        int idx = tid + u * 512;
        int kk = idx & 15, cc = idx >> 4;
        wreg[u] = qkv_w[cc * 128 + kk];           // chunk 0
    }

    const int cb = ty * 24;
    for (int ch = 0; ch < 8; ++ch) {
        __syncthreads();
        #pragma unroll
        for (int u = 0; u < 12; ++u) {
            int idx = tid + u * 512;
            int kk = idx & 15, cc = idx >> 4;
            unsigned uu; CVT_TF32(uu, wreg[u]);
            wt[kk * 392 + cc] = __uint_as_float(uu);
        }
        if (ch < 7) {
            #pragma unroll
            for (int u = 0; u < 12; ++u) {
                int idx = tid + u * 512;
                int kk = idx & 15, cc = idx >> 4;
                wreg[u] = qkv_w[cc * 128 + (ch + 1) * 16 + kk];
            }
        }
        __syncthreads();

        #pragma unroll
        for (int ks = 0; ks < 2; ++ks) {
            int koff = ks * 8;
            unsigned bfr[3][2];
            #pragma unroll
            for (int nt = 0; nt < 3; ++nt) {
                bfr[nt][0] = __float_as_uint(wt[(koff + tig) * 392 + cb + nt * 8 + gid]);
                bfr[nt][1] = __float_as_uint(wt[(koff + tig + 4) * 392 + cb + nt * 8 + gid]);
            }
            #pragma unroll
            for (int mt = 0; mt < 7; ++mt) {
                int i0 = mt * 16 + gid, i1 = i0 + 8;
                int c = ch * 16 + koff + tig;
                unsigned afr[4];
                afr[0] = __float_as_uint(xs[i0 * 128 + ((c + 4 * i0) & 127)]);
                afr[1] = __float_as_uint(xs[i1 * 128 + ((c + 4 * i1) & 127)]);
                afr[2] = __float_as_uint(xs[i0 * 128 + ((c + 4 + 4 * i0) & 127)]);
                afr[3] = __float_as_uint(xs[i1 * 128 + ((c + 4 + 4 * i1) & 127)]);
                #pragma unroll
                for (int nt = 0; nt < 3; ++nt)
                    mma_tf32(facc[mt][nt], afr, bfr[nt]);
            }
        }
    }

    // epilogue: bias add, tf32 convert, write q/kT/vT to global scratch
    #pragma unroll
    for (int nt = 0; nt < 3; ++nt) {
        int c0 = cb + nt * 8 + 2 * tig;
        int sect = c0 >> 7;
        int hh   = (c0 >> 5) & 3;
        int d0   = c0 & 31;
        int wh   = b * HEADS + hh;
        float bi0 = qkv_b[c0], bi1 = qkv_b[c0 + 1];
        #pragma unroll
        for (int mt = 0; mt < 7; ++mt) {
            #pragma unroll
            for (int half = 0; half < 2; ++half) {
                int i = mt * 16 + gid + half * 8;
                if (i >= 98) continue;
                float v0 = facc[mt][nt][half * 2 + 0] + bi0;
                float v1 = facc[mt][nt][half * 2 + 1] + bi1;
                unsigned u0, u1;
                if (sect == 0) {
                    CVT_TF32(u0, v0 * scale);
                    CVT_TF32(u1, v1 * scale);
                    g_q[(size_t)wh * 3136 + i * 32 + d0]     = __uint_as_float(u0);
                    g_q[(size_t)wh * 3136 + i * 32 + d0 + 1] = __uint_as_float(u1);
                } else if (sect == 1) {
                    CVT_TF32(u0, v0);
                    CVT_TF32(u1, v1);
                    g_kT[(size_t)wh * 3328 + d0 * 104 + i]       = __uint_as_float(u0);
                    g_kT[(size_t)wh * 3328 + (d0 + 1) * 104 + i] = __uint_as_float(u1);
                } else {
                    CVT_TF32(u0, v0);
                    CVT_TF32(u1, v1);
                    g_vT[(size_t)wh * 3328 + d0 * 104 + i]       = __uint_as_float(u0);
                    g_vT[(size_t)wh * 3328 + (d0 + 1) * 104 + i] = __uint_as_float(u1);
                }
            }
        }
    }
}

// =================== Kernel B: attention (grid NWIN*HEADS, 224 thr) ===================
__global__ __launch_bounds__(224)
void attn_kernel(const float* __restrict__ mask)
{
    __shared__ float ks_s[32 * 104];
    __shared__ float vs_s[32 * 104];

    const int wh  = blockIdx.x;
    const int b   = wh >> 2;
    const int h   = wh & 3;
    const int tid = threadIdx.x;
    const int tx  = tid & 31;
    const int ty  = tid >> 5;            // warp 0..6 = m-tile
    const int gid = tx >> 2;
    const int tig = tx & 3;

    // load kT/vT tiles (pads are zero in global scratch)
    {
        const float4* kg = (const float4*)(g_kT + (size_t)wh * 3328);
        const float4* vg = (const float4*)(g_vT + (size_t)wh * 3328);
        for (int i = tid; i < 832; i += 224) {
            ((float4*)ks_s)[i] = kg[i];
            ((float4*)vs_s)[i] = vg[i];
        }
    }
    __syncthreads();

    const int mt = ty;
    const int i0 = mt * 16 + gid, i1 = i0 + 8;
    const bool val0 = i0 < 98, val1 = i1 < 98;
    const int i0c = val0 ? i0 : 97, i1c = val1 ? i1 : 97;
    const float* qg = g_q + (size_t)wh * 3136;
    const float* bh = g_bias + h * (N_TOK * N_TOK);
    const float* maskp = mask + (size_t)(b & (LWIN - 1)) * (N_TOK * N_TOK);
    const int qsrc0 = (tx & ~3) | (tig >> 1);
    const int qsrc1 = qsrc0 | 2;
    const bool odd = tig & 1;

    // ---- init S frags with bias + mask (LDGs issue before mma) ----
    float s[13][4];
    #pragma unroll
    for (int nt = 0; nt < 13; ++nt) {
        int j0 = nt * 8 + 2 * tig;
        if (j0 < 98) {
            if (val0) {
                float2 bb = *(const float2*)(bh + i0 * 98 + j0);
                float2 mm = *(const float2*)(maskp + i0 * 98 + j0);
                s[nt][0] = bb.x + mm.x;
                s[nt][1] = bb.y + mm.y;
            } else { s[nt][0] = s[nt][1] = 0.f; }
            if (val1) {
                float2 bb = *(const float2*)(bh + i1 * 98 + j0);
                float2 mm = *(const float2*)(maskp + i1 * 98 + j0);
                s[nt][2] = bb.x + mm.x;
                s[nt][3] = bb.y + mm.y;
            } else { s[nt][2] = s[nt][3] = 0.f; }
        } else {
            s[nt][0] = s[nt][1] = s[nt][2] = s[nt][3] = -1e30f;
        }
    }

    // ---- S += q k^T ----
    #pragma unroll
    for (int ksi = 0; ksi < 4; ++ksi) {
        int d = ksi * 8 + tig;
        unsigned a[4];
        a[0] = __float_as_uint(qg[i0c * 32 + d]);
        a[1] = __float_as_uint(qg[i1c * 32 + d]);
        a[2] = __float_as_uint(qg[i0c * 32 + d + 4]);
        a[3] = __float_as_uint(qg[i1c * 32 + d + 4]);
        #pragma unroll
        for (int nt = 0; nt < 13; ++nt) {
            unsigned bb[2];
            bb[0] = __float_as_uint(ks_s[d * 104 + nt * 8 + gid]);
            bb[1] = __float_as_uint(ks_s[(d + 4) * 104 + nt * 8 + gid]);
            mma_tf32(s[nt], a, bb);
        }
    }

    // ---- softmax on fragments ----
    float m0 = -1e30f, m1 = -1e30f;
    #pragma unroll
    for (int nt = 0; nt < 13; ++nt) {
        m0 = fmaxf(m0, fmaxf(s[nt][0], s[nt][1]));
        m1 = fmaxf(m1, fmaxf(s[nt][2], s[nt][3]));
    }
    m0 = fmaxf(m0, __shfl_xor_sync(0xffffffffu, m0, 1));
    m0 = fmaxf(m0, __shfl_xor_sync(0xffffffffu, m0, 2));
    m1 = fmaxf(m1, __shfl_xor_sync(0xffffffffu, m1, 1));
    m1 = fmaxf(m1, __shfl_xor_sync(0xffffffffu, m1, 2));

    float z0 = 0.f, z1 = 0.f;
    #pragma unroll
    for (int nt = 0; nt < 13; ++nt) {
        s[nt][0] = __expf(s[nt][0] - m0);
        s[nt][1] = __expf(s[nt][1] - m0);
        s[nt][2] = __expf(s[nt][2] - m1);
        s[nt][3] = __expf(s[nt][3] - m1);
        z0 += s[nt][0] + s[nt][1];
        z1 += s[nt][2] + s[nt][3];
    }
    z0 += __shfl_xor_sync(0xffffffffu, z0, 1);
    z0 += __shfl_xor_sync(0xffffffffu, z0, 2);
    z1 += __shfl_xor_sync(0xffffffffu, z1, 1);
    z1 += __shfl_xor_sync(0xffffffffu, z1, 2);
    float inv0 = 1.f / z0, inv1 = 1.f / z1;

    // ---- O = P @ V ; P C-frags -> A-frags via quad shuffles ----
    float o[4][4];
    #pragma unroll
    for (int nt = 0; nt < 4; ++nt)
        #pragma unroll
        for (int e = 0; e < 4; ++e) o[nt][e] = 0.f;

    #pragma unroll
    for (int jt = 0; jt < 13; ++jt) {
        float t00 = __shfl_sync(0xffffffffu, s[jt][0], qsrc0);
        float t01 = __shfl_sync(0xffffffffu, s[jt][1], qsrc0);
        float t10 = __shfl_sync(0xffffffffu, s[jt][2], qsrc0);
        float t11 = __shfl_sync(0xffffffffu, s[jt][3], qsrc0);
        float t20 = __shfl_sync(0xffffffffu, s[jt][0], qsrc1);
        float t21 = __shfl_sync(0xffffffffu, s[jt][1], qsrc1);
        float t30 = __shfl_sync(0xffffffffu, s[jt][2], qsrc1);
        float t31 = __shfl_sync(0xffffffffu, s[jt][3], qsrc1);
        unsigned pa[4];
        CVT_TF32(pa[0], odd ? t01 : t00);
        CVT_TF32(pa[1], odd ? t11 : t10);
        CVT_TF32(pa[2], odd ? t21 : t20);
        CVT_TF32(pa[3], odd ? t31 : t30);
        #pragma unroll
        for (int nt = 0; nt < 4; ++nt) {
            unsigned bb[2];
            bb[0] = __float_as_uint(vs_s[(nt * 8 + gid) * 104 + jt * 8 + tig]);
            bb[1] = __float_as_uint(vs_s[(nt * 8 + gid) * 104 + jt * 8 + tig + 4]);
            mma_tf32(o[nt], pa, bb);
        }
    }

    // ---- store O (normalized, tf32 bits) swizzled per window ----
    float* og = g_O + (size_t)b * (N_TOK * CDIM);
    #pragma unroll
    for (int nt = 0; nt < 4; ++nt) {
        int C = h * 32 + nt * 8 + 2 * tig;
        if (val0) {
            unsigned u0, u1;
            CVT_TF32(u0, o[nt][0] * inv0);
            CVT_TF32(u1, o[nt][1] * inv0);
            float2 w2; w2.x = __uint_as_float(u0); w2.y = __uint_as_float(u1);
            *(float2*)(og + i0 * 128 + ((C + 4 * i0) & 127)) = w2;
        }
        if (val1) {
            unsigned u0, u1;
            CVT_TF32(u0, o[nt][2] * inv1);
            CVT_TF32(u1, o[nt][3] * inv1);
            float2 w2; w2.x = __uint_as_float(u0); w2.y = __uint_as_float(u1);
            *(float2*)(og + i1 * 128 + ((C + 4 * i1) & 127)) = w2;
        }
    }
}

// =================== Kernel C: projection (grid NWIN, 512 thr) ===================
// smem: xs [0..12544) O tile (tf32 bits, swizzled); wt [12544..14720) 16x136 chunk
#define C_SMEM_FLOATS 14720

__global__ __launch_bounds__(512)
void proj_kernel(const float* __restrict__ proj_w,
                 const float* __restrict__ proj_b,
                 float* __restrict__ out)
{
    extern __shared__ float sm[];
    float* xs = sm;
    float* wt = sm + 12544;

    const int b   = blockIdx.x;
    const int tid = threadIdx.x;
    const int tx  = tid & 31;
    const int ty  = tid >> 5;
    const int gid = tx >> 2;
    const int tig = tx & 3;

    // load O tile (already tf32 bits + swizzled)
    {
        const float4* og4 = (const float4*)(g_O + (size_t)b * (N_TOK * CDIM));
        for (int i = tid; i < N_TOK * 32; i += 512)
            ((float4*)xs)[i] = og4[i];
    }

    float facc[7][4];
    #pragma unroll
    for (int mt = 0; mt < 7; ++mt)
        #pragma unroll
        for (int e = 0; e < 4; ++e) facc[mt][e] = 0.f;

    float preg[4];
    #pragma unroll
    for (int u = 0; u < 4; ++u) {
        int idx = tid + u * 512;
        int kk = idx & 15, cc = idx >> 4;
        preg[u] = proj_w[cc * 128 + kk];          // chunk 0
    }

    const int cb = ty * 8;
    for (int ch = 0; ch < 8; ++ch) {
        __syncthreads();   // first iter: covers O STS; later: wt reuse
        #pragma unroll
        for (int u = 0; u < 4; ++u) {
            int idx = tid + u * 512;
            int kk = idx & 15, cc = idx >> 4;
            unsigned uu; CVT_TF32(uu, preg[u]);
            wt[kk * 136 + cc] = __uint_as_float(uu);
        }
        if (ch < 7) {
            #pragma unroll
            for (int u = 0; u < 4; ++u) {
                int idx = tid + u * 512;
                int kk = idx & 15, cc = idx >> 4;
                preg[u] = proj_w[cc * 128 + (ch + 1) * 16 + kk];
            }
        }
        __syncthreads();

        #pragma unroll
        for (int ksi = 0; ksi < 2; ++ksi) {
            int koff = ksi * 8;
            unsigned bfr[2];
            bfr[0] = __float_as_uint(wt[(koff + tig) * 136 + cb + gid]);
            bfr[1] = __float_as_uint(wt[(koff + tig + 4) * 136 + cb + gid]);
            #pragma unroll
            for (int mt = 0; mt < 7; ++mt) {
                int i0 = mt * 16 + gid, i1 = i0 + 8;
                int c = ch * 16 + koff + tig;
                unsigned afr[4];
                afr[0] = __float_as_uint(xs[i0 * 128 + ((c + 4 * i0) & 127)]);
                afr[1] = __float_as_uint(xs[i1 * 128 + ((c + 4 * i1) & 127)]);
                afr[2] = __float_as_uint(xs[i0 * 128 + ((c + 4 + 4 * i0) & 127)]);
                afr[3] = __float_as_uint(xs[i1 * 128 + ((c + 4 + 4 * i1) & 127)]);
                mma_tf32(facc[mt], afr, bfr);
            }
        }
    }

    float pb0 = proj_b[cb + 2 * tig];
    float pb1 = proj_b[cb + 2 * tig + 1];
    float* outb = out + (size_t)b * (N_TOK * CDIM);
    #pragma unroll
    for (int mt = 0; mt < 7; ++mt) {
        #pragma unroll
        for (int half = 0; half < 2; ++half) {
            int i = mt * 16 + gid + half * 8;
            if (i >= 98) continue;
            float2 v;
            v.x = facc[mt][half * 2 + 0] + pb0;
            v.y = facc[mt][half * 2 + 1] + pb1;
            *(float2*)(outb + i * 128 + cb + 2 * tig) = v;
        }
    }
}

extern "C" void kernel_launch(void* const* d_in, const int* in_sizes, int n_in,
                              void* d_out, int out_size)
{
    const float* x      = (const float*)d_in[0];
    const float* mask   = (const float*)d_in[1];
    const float* qkv_w  = (const float*)d_in[2];
    const float* qkv_b  = (const float*)d_in[3];
    const float* pe     = (const float*)d_in[4];
    const float* proj_w = (const float*)d_in[5];
    const float* proj_b = (const float*)d_in[6];
    float* out = (float*)d_out;

    int nwin = in_sizes[0] / (N_TOK * CDIM);              // 2048

    bias_precompute_kernel<<<(HEADS * N_TOK * N_TOK + 255) / 256, 256>>>(pe);

    cudaFuncSetAttribute(qkv_kernel,
                         cudaFuncAttributeMaxDynamicSharedMemorySize,
                         A_SMEM_FLOATS * (int)sizeof(float));
    cudaFuncSetAttribute(proj_kernel,
                         cudaFuncAttributeMaxDynamicSharedMemorySize,
                         C_SMEM_FLOATS * (int)sizeof(float));

    qkv_kernel<<<nwin, 512, A_SMEM_FLOATS * sizeof(float)>>>(x, qkv_w, qkv_b);
    attn_kernel<<<nwin * HEADS, 224>>>(mask);
    proj_kernel<<<nwin, 512, C_SMEM_FLOATS * sizeof(float)>>>(proj_w, proj_b, out);
}